// round 10
// baseline (speedup 1.0000x reference)
#include <cuda_runtime.h>
#include <cuda_fp16.h>
#include <cstdint>

// out[16384,1280] = x[16384,1280] @ A[1280,1280],  A = (k1 (x) k2 (x) k3) @ W^T
// Kron factorization in fp32, then SINGLE-product fp16 HMMA GEMM:
//   D = fp16(x) * fp16(A^T)   (fp32 accumulate)  rel_err ~2.9e-4 (validated)
// R9: stage kernels rebuilt as smem-tiled small matmuls (40x re-read eliminated);
// cvt_x 8 elems/thread. GEMM unchanged from R8 (single barrier, NSTAGE=5).

#define DD 1280
#define MROWS 16384

__device__ float g_buf0[DD * DD];
__device__ float g_buf1[DD * DD];
__device__ float g_k12[32 * 32];
__device__ __half g_Xh[(size_t)MROWS * DD];
__device__ __half g_Ath[DD * DD];   // fp16(A^T): [n][k], k contiguous

// ---------------------------------------------------------------------------
__device__ __forceinline__ uint32_t smem_u32(const void* p) {
    uint32_t a;
    asm("{ .reg .u64 t; cvta.to.shared.u64 t, %1; cvt.u32.u64 %0, t; }" : "=r"(a) : "l"(p));
    return a;
}
__device__ __forceinline__ void ldsm_x4(uint32_t* r, uint32_t addr) {
    asm volatile("ldmatrix.sync.aligned.m8n8.x4.shared.b16 {%0,%1,%2,%3}, [%4];"
                 : "=r"(r[0]), "=r"(r[1]), "=r"(r[2]), "=r"(r[3]) : "r"(addr));
}
__device__ __forceinline__ void mma_f16(float* c, const uint32_t* a, const uint32_t* b) {
    asm volatile("mma.sync.aligned.m16n8k16.row.col.f32.f16.f16.f32 "
                 "{%0,%1,%2,%3}, {%4,%5,%6,%7}, {%8,%9}, {%0,%1,%2,%3};"
                 : "+f"(c[0]), "+f"(c[1]), "+f"(c[2]), "+f"(c[3])
                 : "r"(a[0]), "r"(a[1]), "r"(a[2]), "r"(a[3]), "r"(b[0]), "r"(b[1]));
}
#define CP16(dst, src) \
    asm volatile("cp.async.cg.shared.global [%0], [%1], 16;" :: "r"(dst), "l"(src))
#define CP_COMMIT() asm volatile("cp.async.commit_group;" ::: "memory")
#define CP_WAIT3()  asm volatile("cp.async.wait_group 3;" ::: "memory")

// ---------------------------------------------------------------------------
// Prologue chain (fp32)
// ---------------------------------------------------------------------------
__global__ void transpose_kernel(const float* __restrict__ W, float* __restrict__ Wt) {
    __shared__ float tile[32][33];
    const int j0 = blockIdx.x * 32, o0 = blockIdx.y * 32;
    const int tx = threadIdx.x, ty = threadIdx.y;
#pragma unroll
    for (int r = 0; r < 32; r += 8)
        tile[ty + r][tx] = W[(o0 + ty + r) * DD + (j0 + tx)];
    __syncthreads();
#pragma unroll
    for (int r = 0; r < 32; r += 8)
        Wt[(j0 + ty + r) * DD + (o0 + tx)] = tile[tx][ty + r];
}
// k12 = kron(k1, k2): k12[a1*8+a2][b1*8+b2] = k1[a1][b1]*k2[a2][b2]
__global__ void kron12_kernel(const float* __restrict__ k1, const float* __restrict__ k2,
                              float* __restrict__ k12) {
    const int t = threadIdx.x;              // 0..1023
    const int r = t >> 5, c = t & 31;
    k12[t] = k1[(r >> 3) * 4 + (c >> 3)] * k2[(r & 7) * 8 + (c & 7)];
}
// Stage 3 as smem-tiled matmul: block (o-tile 128, g) computes
// dst[(g*40+a3)][o] = sum_b3 k3[a3][b3] * src[(g*40+b3)][o], all 40 a3 at once.
__global__ __launch_bounds__(256)
void stage3_kernel(const float* __restrict__ src, float* __restrict__ dst,
                   const float* __restrict__ k3) {
    __shared__ float sin_[40][128];
    __shared__ float sk[40][40];
    const int tid = threadIdx.x;
    const int o0 = blockIdx.x * 128, g = blockIdx.y;
    for (int i = tid; i < 40 * 128; i += 256) {
        int r = i >> 7, c = i & 127;
        sin_[r][c] = src[(g * 40 + r) * DD + o0 + c];
    }
    for (int i = tid; i < 1600; i += 256) sk[i / 40][i % 40] = k3[i];
    __syncthreads();
    const int o = tid & 127;
    for (int a3 = tid >> 7; a3 < 40; a3 += 2) {
        float acc = 0.f;
#pragma unroll 8
        for (int b3 = 0; b3 < 40; b3++) acc += sk[a3][b3] * sin_[b3][o];
        dst[(g * 40 + a3) * DD + o0 + o] = acc;
    }
}
// Fused stage2+stage1 as smem-tiled matmul: block (o-tile 128, a3) computes
// dst[(c12*40+a3)][o] = sum_b12 k12[c12][b12] * src[(b12*40+a3)][o], 32 c12 at once.
__global__ __launch_bounds__(256)
void stage12_kernel(const float* __restrict__ src, float* __restrict__ dst,
                    const float* __restrict__ k12) {
    __shared__ float sin_[32][128];
    __shared__ float sk[32][32];
    const int tid = threadIdx.x;
    const int o0 = blockIdx.x * 128, a3 = blockIdx.y;
    for (int i = tid; i < 32 * 128; i += 256) {
        int r = i >> 7, c = i & 127;
        sin_[r][c] = src[(r * 40 + a3) * DD + o0 + c];
    }
    for (int i = tid; i < 1024; i += 256) sk[i >> 5][i & 31] = k12[i];
    __syncthreads();
    const int o = tid & 127;
    for (int c12 = tid >> 7; c12 < 32; c12 += 2) {
        float acc = 0.f;
#pragma unroll 8
        for (int b12 = 0; b12 < 32; b12++) acc += sk[c12][b12] * sin_[b12][o];
        dst[(c12 * 40 + a3) * DD + o0 + o] = acc;
    }
}
// x -> fp16, 8 elems/thread
__global__ void cvt_x_kernel(const float* __restrict__ x, __half* __restrict__ xh) {
    const size_t i8 = ((size_t)blockIdx.x * 256 + threadIdx.x) * 8;
    float4 v0 = *reinterpret_cast<const float4*>(x + i8);
    float4 v1 = *reinterpret_cast<const float4*>(x + i8 + 4);
    __half2 a = __floats2half2_rn(v0.x, v0.y);
    __half2 b = __floats2half2_rn(v0.z, v0.w);
    __half2 c = __floats2half2_rn(v1.x, v1.y);
    __half2 d = __floats2half2_rn(v1.z, v1.w);
    uint4 o;
    o.x = *reinterpret_cast<uint32_t*>(&a);
    o.y = *reinterpret_cast<uint32_t*>(&b);
    o.z = *reinterpret_cast<uint32_t*>(&c);
    o.w = *reinterpret_cast<uint32_t*>(&d);
    *reinterpret_cast<uint4*>(xh + i8) = o;
}
// A[k][n] -> fp16(At[n][k])
__global__ void cvt_at_kernel(const float* __restrict__ A, __half* __restrict__ ath) {
    __shared__ float t[32][33];
    const int k0 = blockIdx.x * 32, n0 = blockIdx.y * 32;
    const int tx = threadIdx.x, ty = threadIdx.y;
#pragma unroll
    for (int r = 0; r < 32; r += 8)
        t[ty + r][tx] = A[(k0 + ty + r) * DD + (n0 + tx)];
    __syncthreads();
#pragma unroll
    for (int r = 0; r < 32; r += 8)
        ath[(n0 + ty + r) * DD + (k0 + tx)] = __float2half_rn(t[tx][ty + r]);
}

// ---------------------------------------------------------------------------
// Single-product fp16 HMMA GEMM. CTA tile 128x128, BK=32, 256 threads,
// NSTAGE=5, 2 CTAs/SM, ONE barrier per ktile. (unchanged from R8 — validated)
// ---------------------------------------------------------------------------
#define BK 32
#define PADK 40
#define XTB (128 * PADK * 2)        // 10240 B per tile
#define STB (2 * XTB)               // stage: Xh, Ath = 20480 B
#define NSTAGE 5
#define GEMM_SMEM (NSTAGE * STB)    // 102400 B
#define KTILES (DD / BK)            // 40

__device__ __forceinline__ void load_stage_async(
    uint32_t sdst,
    const __half* __restrict__ Xh, const __half* __restrict__ Ath,
    int bm, int bn, int kt, int tid) {
    const int kofs = kt * BK;
#pragma unroll
    for (int i = 0; i < 2; i++) {
        int idx = i * 256 + tid;          // 0..511
        int row = idx >> 2, c = idx & 3;  // 4 x 16B chunks per 64B data row
        uint32_t so = (uint32_t)(row * (PADK * 2) + c * 16);
        size_t gx = (size_t)(bm * 128 + row) * DD + kofs + c * 8;
        size_t ga = (size_t)(bn * 128 + row) * DD + kofs + c * 8;
        CP16(sdst + so,       Xh  + gx);
        CP16(sdst + XTB + so, Ath + ga);
    }
}

__global__ __launch_bounds__(256, 2)
void gemm_hmma_kernel(const __half* __restrict__ Xh,
                      const __half* __restrict__ Ath,
                      float* __restrict__ out) {
    extern __shared__ __align__(128) char smem[];
    const uint32_t sbase = smem_u32(smem);
    const int tid = threadIdx.x, lane = tid & 31, wid = tid >> 5;
    const int warp_m = wid & 3, warp_n = wid >> 2;   // 4 x 2 warps, tile 32x64
    const int bn = blockIdx.x, bm = blockIdx.y;

    float acc[2][8][4];
#pragma unroll
    for (int a = 0; a < 2; a++)
#pragma unroll
        for (int b = 0; b < 8; b++)
#pragma unroll
            for (int c = 0; c < 4; c++) acc[a][b][c] = 0.f;

#pragma unroll
    for (int p = 0; p < 4; p++) {
        load_stage_async(sbase + (uint32_t)p * STB, Xh, Ath, bm, bn, p, tid);
        CP_COMMIT();
    }

    const uint32_t a_row = (uint32_t)(warp_m * 32 + (lane & 7) + ((lane >> 3) & 1) * 8);
    const uint32_t a_colb = (uint32_t)(((lane >> 4) & 1) * 8) * 2;
    const uint32_t b_nrow = (uint32_t)(warp_n * 64 + (lane & 7) + ((lane >> 4) & 1) * 8);
    const uint32_t b_kb = (uint32_t)(((lane >> 3) & 1) * 8) * 2;

    for (int kt = 0; kt < KTILES; kt++) {
        CP_WAIT3();
        __syncthreads();   // single barrier per ktile (stage being overwritten was
                           // last read in iteration kt-1; this barrier separates them)
        const uint32_t st = sbase + (uint32_t)(kt % NSTAGE) * STB;
        const uint32_t sX = st, sA = st + XTB;
#pragma unroll
        for (int kk = 0; kk < 2; kk++) {
            const uint32_t acol = a_colb + kk * 32;
            const uint32_t bcol = b_kb + kk * 32;
            uint32_t ax[2][4];
            ldsm_x4(ax[0], sX + a_row * (PADK * 2) + acol);
            ldsm_x4(ax[1], sX + (a_row + 16) * (PADK * 2) + acol);
            uint32_t bb[8][2];
#pragma unroll
            for (int j = 0; j < 4; j++) {
                uint32_t r[4];
                ldsm_x4(r, sA + (b_nrow + j * 16) * (PADK * 2) + bcol);
                bb[2 * j][0] = r[0]; bb[2 * j][1] = r[1];
                bb[2 * j + 1][0] = r[2]; bb[2 * j + 1][1] = r[3];
            }
#pragma unroll
            for (int mi = 0; mi < 2; mi++)
#pragma unroll
                for (int nj = 0; nj < 8; nj++)
                    mma_f16(acc[mi][nj], ax[mi], bb[nj]);
        }
        if (kt + 4 < KTILES)
            load_stage_async(sbase + (uint32_t)((kt + 4) % NSTAGE) * STB,
                             Xh, Ath, bm, bn, kt + 4, tid);
        CP_COMMIT();   // unconditional: keeps wait_group(3) retiring correctly
    }

    // epilogue
    const int er = lane >> 2, ec = (lane & 3) * 2;
#pragma unroll
    for (int mi = 0; mi < 2; mi++) {
        const int row = bm * 128 + warp_m * 32 + mi * 16 + er;
#pragma unroll
        for (int nt = 0; nt < 8; nt++) {
            const int col = bn * 128 + warp_n * 64 + nt * 8 + ec;
            *reinterpret_cast<float2*>(out + (size_t)row * DD + col) =
                make_float2(acc[mi][nt][0], acc[mi][nt][1]);
            *reinterpret_cast<float2*>(out + (size_t)(row + 8) * DD + col) =
                make_float2(acc[mi][nt][2], acc[mi][nt][3]);
        }
    }
}

// ---------------------------------------------------------------------------
extern "C" void kernel_launch(void* const* d_in, const int* in_sizes, int n_in,
                              void* d_out, int out_size) {
    const float* x  = (const float*)d_in[0];
    const float* W  = (const float*)d_in[1];
    const float* k1 = (const float*)d_in[2];
    const float* k2 = (const float*)d_in[3];
    const float* k3 = (const float*)d_in[4];
    float* out = (float*)d_out;

    float *buf0, *buf1, *k12;
    __half *xh, *ath;
    cudaGetSymbolAddress((void**)&buf0, g_buf0);
    cudaGetSymbolAddress((void**)&buf1, g_buf1);
    cudaGetSymbolAddress((void**)&k12, g_k12);
    cudaGetSymbolAddress((void**)&xh, g_Xh);
    cudaGetSymbolAddress((void**)&ath, g_Ath);

    {
        size_t n8 = (size_t)MROWS * DD / 8;
        cvt_x_kernel<<<(unsigned)(n8 / 256), 256>>>(x, xh);
    }
    kron12_kernel<<<1, 1024>>>(k1, k2, k12);
    {
        dim3 grid(DD / 32, DD / 32), block(32, 8);
        transpose_kernel<<<grid, block>>>(W, buf0);
    }
    {
        dim3 g3(DD / 128, 32);                 // (o-tile, g)
        stage3_kernel<<<g3, 256>>>(buf0, buf1, k3);    // buf1 = T1
        dim3 g12(DD / 128, 40);                // (o-tile, a3)
        stage12_kernel<<<g12, 256>>>(buf1, buf0, k12); // buf0 = A
    }
    {
        dim3 grid(DD / 32, DD / 32), block(32, 8);
        cvt_at_kernel<<<grid, block>>>(buf0, ath);
    }
    {
        static bool attr_set = false;
        if (!attr_set) {
            cudaFuncSetAttribute(gemm_hmma_kernel,
                                 cudaFuncAttributeMaxDynamicSharedMemorySize, GEMM_SMEM);
            attr_set = true;
        }
        dim3 grid(DD / 128, MROWS / 128);   // (10, 128)
        gemm_hmma_kernel<<<grid, 256, GEMM_SMEM>>>(xh, ath, out);
    }
}

// round 11
// speedup vs baseline: 1.0450x; 1.0450x over previous
#include <cuda_runtime.h>
#include <cuda_fp16.h>
#include <cstdint>

// out[16384,1280] = x[16384,1280] @ A[1280,1280],  A = (k1 (x) k2 (x) k3) @ W^T
// Kron factorization in fp32, then SINGLE-product fp16 HMMA GEMM:
//   D = fp16(x) * fp16(A^T)   (fp32 accumulate)  rel_err ~2.9e-4 (validated)
// R10: stage kernels reverted to the validated R1 shape (1 col/thread, 6400
// light CTAs — fastest measured at 8-9us each); keep k12 fusion, keep R8 GEMM.

#define DD 1280
#define MROWS 16384

__device__ float g_buf0[DD * DD];
__device__ float g_buf1[DD * DD];
__device__ float g_k12[32 * 32];
__device__ __half g_Xh[(size_t)MROWS * DD];
__device__ __half g_Ath[DD * DD];   // fp16(A^T): [n][k], k contiguous

// ---------------------------------------------------------------------------
__device__ __forceinline__ uint32_t smem_u32(const void* p) {
    uint32_t a;
    asm("{ .reg .u64 t; cvta.to.shared.u64 t, %1; cvt.u32.u64 %0, t; }" : "=r"(a) : "l"(p));
    return a;
}
__device__ __forceinline__ void ldsm_x4(uint32_t* r, uint32_t addr) {
    asm volatile("ldmatrix.sync.aligned.m8n8.x4.shared.b16 {%0,%1,%2,%3}, [%4];"
                 : "=r"(r[0]), "=r"(r[1]), "=r"(r[2]), "=r"(r[3]) : "r"(addr));
}
__device__ __forceinline__ void mma_f16(float* c, const uint32_t* a, const uint32_t* b) {
    asm volatile("mma.sync.aligned.m16n8k16.row.col.f32.f16.f16.f32 "
                 "{%0,%1,%2,%3}, {%4,%5,%6,%7}, {%8,%9}, {%0,%1,%2,%3};"
                 : "+f"(c[0]), "+f"(c[1]), "+f"(c[2]), "+f"(c[3])
                 : "r"(a[0]), "r"(a[1]), "r"(a[2]), "r"(a[3]), "r"(b[0]), "r"(b[1]));
}
#define CP16(dst, src) \
    asm volatile("cp.async.cg.shared.global [%0], [%1], 16;" :: "r"(dst), "l"(src))
#define CP_COMMIT() asm volatile("cp.async.commit_group;" ::: "memory")
#define CP_WAIT3()  asm volatile("cp.async.wait_group 3;" ::: "memory")

// ---------------------------------------------------------------------------
// Prologue chain (fp32)
// ---------------------------------------------------------------------------
__global__ void transpose_kernel(const float* __restrict__ W, float* __restrict__ Wt) {
    __shared__ float tile[32][33];
    const int j0 = blockIdx.x * 32, o0 = blockIdx.y * 32;
    const int tx = threadIdx.x, ty = threadIdx.y;
#pragma unroll
    for (int r = 0; r < 32; r += 8)
        tile[ty + r][tx] = W[(o0 + ty + r) * DD + (j0 + tx)];
    __syncthreads();
#pragma unroll
    for (int r = 0; r < 32; r += 8)
        Wt[(j0 + ty + r) * DD + (o0 + tx)] = tile[tx][ty + r];
}
// k12 = kron(k1, k2): k12[a1*8+a2][b1*8+b2] = k1[a1][b1]*k2[a2][b2]
__global__ void kron12_kernel(const float* __restrict__ k1, const float* __restrict__ k2,
                              float* __restrict__ k12) {
    const int t = threadIdx.x;              // 0..1023
    const int r = t >> 5, c = t & 31;
    k12[t] = k1[(r >> 3) * 4 + (c >> 3)] * k2[(r & 7) * 8 + (c & 7)];
}
// Stage 3 (R1 shape): T1[(g*40+a3)][o] = sum_b3 k3[a3][b3]*Wt[(g*40+b3)][o]
__global__ void stage3_kernel(const float* __restrict__ src, float* __restrict__ dst,
                              const float* __restrict__ k3) {
    const int o = blockIdx.x * 256 + threadIdx.x;
    const int i = blockIdx.y;
    const int g = i / 40, a3 = i % 40;
    __shared__ float krow[40];
    if (threadIdx.x < 40) krow[threadIdx.x] = k3[a3 * 40 + threadIdx.x];
    __syncthreads();
    const float* s = src + (g * 40) * DD + o;
    float acc = 0.f;
#pragma unroll 8
    for (int b3 = 0; b3 < 40; b3++) acc += krow[b3] * s[b3 * DD];
    dst[i * DD + o] = acc;
}
// Fused stage2+stage1 (R1 shape, 32-term via k12):
// A[(c12*40+a3)][o] = sum_b12 k12[c12][b12]*T1[(b12*40+a3)][o]
__global__ void stage12_kernel(const float* __restrict__ src, float* __restrict__ dst,
                               const float* __restrict__ k12) {
    const int o = blockIdx.x * 256 + threadIdx.x;
    const int i = blockIdx.y;
    const int c12 = i / 40, a3 = i % 40;
    __shared__ float krow[32];
    if (threadIdx.x < 32) krow[threadIdx.x] = k12[c12 * 32 + threadIdx.x];
    __syncthreads();
    const float* s = src + a3 * DD + o;
    float acc = 0.f;
#pragma unroll 8
    for (int b12 = 0; b12 < 32; b12++) acc += krow[b12] * s[b12 * 40 * DD];
    dst[i * DD + o] = acc;
}
// x -> fp16, 8 elems/thread
__global__ void cvt_x_kernel(const float* __restrict__ x, __half* __restrict__ xh) {
    const size_t i8 = ((size_t)blockIdx.x * 256 + threadIdx.x) * 8;
    float4 v0 = *reinterpret_cast<const float4*>(x + i8);
    float4 v1 = *reinterpret_cast<const float4*>(x + i8 + 4);
    __half2 a = __floats2half2_rn(v0.x, v0.y);
    __half2 b = __floats2half2_rn(v0.z, v0.w);
    __half2 c = __floats2half2_rn(v1.x, v1.y);
    __half2 d = __floats2half2_rn(v1.z, v1.w);
    uint4 o;
    o.x = *reinterpret_cast<uint32_t*>(&a);
    o.y = *reinterpret_cast<uint32_t*>(&b);
    o.z = *reinterpret_cast<uint32_t*>(&c);
    o.w = *reinterpret_cast<uint32_t*>(&d);
    *reinterpret_cast<uint4*>(xh + i8) = o;
}
// A[k][n] -> fp16(At[n][k])
__global__ void cvt_at_kernel(const float* __restrict__ A, __half* __restrict__ ath) {
    __shared__ float t[32][33];
    const int k0 = blockIdx.x * 32, n0 = blockIdx.y * 32;
    const int tx = threadIdx.x, ty = threadIdx.y;
#pragma unroll
    for (int r = 0; r < 32; r += 8)
        t[ty + r][tx] = A[(k0 + ty + r) * DD + (n0 + tx)];
    __syncthreads();
#pragma unroll
    for (int r = 0; r < 32; r += 8)
        ath[(n0 + ty + r) * DD + (k0 + tx)] = __float2half_rn(t[tx][ty + r]);
}

// ---------------------------------------------------------------------------
// Single-product fp16 HMMA GEMM. CTA tile 128x128, BK=32, 256 threads,
// NSTAGE=5, 2 CTAs/SM, ONE barrier per ktile. (validated R8 config)
// ---------------------------------------------------------------------------
#define BK 32
#define PADK 40
#define XTB (128 * PADK * 2)        // 10240 B per tile
#define STB (2 * XTB)               // stage: Xh, Ath = 20480 B
#define NSTAGE 5
#define GEMM_SMEM (NSTAGE * STB)    // 102400 B
#define KTILES (DD / BK)            // 40

__device__ __forceinline__ void load_stage_async(
    uint32_t sdst,
    const __half* __restrict__ Xh, const __half* __restrict__ Ath,
    int bm, int bn, int kt, int tid) {
    const int kofs = kt * BK;
#pragma unroll
    for (int i = 0; i < 2; i++) {
        int idx = i * 256 + tid;          // 0..511
        int row = idx >> 2, c = idx & 3;  // 4 x 16B chunks per 64B data row
        uint32_t so = (uint32_t)(row * (PADK * 2) + c * 16);
        size_t gx = (size_t)(bm * 128 + row) * DD + kofs + c * 8;
        size_t ga = (size_t)(bn * 128 + row) * DD + kofs + c * 8;
        CP16(sdst + so,       Xh  + gx);
        CP16(sdst + XTB + so, Ath + ga);
    }
}

__global__ __launch_bounds__(256, 2)
void gemm_hmma_kernel(const __half* __restrict__ Xh,
                      const __half* __restrict__ Ath,
                      float* __restrict__ out) {
    extern __shared__ __align__(128) char smem[];
    const uint32_t sbase = smem_u32(smem);
    const int tid = threadIdx.x, lane = tid & 31, wid = tid >> 5;
    const int warp_m = wid & 3, warp_n = wid >> 2;   // 4 x 2 warps, tile 32x64
    const int bn = blockIdx.x, bm = blockIdx.y;

    float acc[2][8][4];
#pragma unroll
    for (int a = 0; a < 2; a++)
#pragma unroll
        for (int b = 0; b < 8; b++)
#pragma unroll
            for (int c = 0; c < 4; c++) acc[a][b][c] = 0.f;

#pragma unroll
    for (int p = 0; p < 4; p++) {
        load_stage_async(sbase + (uint32_t)p * STB, Xh, Ath, bm, bn, p, tid);
        CP_COMMIT();
    }

    const uint32_t a_row = (uint32_t)(warp_m * 32 + (lane & 7) + ((lane >> 3) & 1) * 8);
    const uint32_t a_colb = (uint32_t)(((lane >> 4) & 1) * 8) * 2;
    const uint32_t b_nrow = (uint32_t)(warp_n * 64 + (lane & 7) + ((lane >> 4) & 1) * 8);
    const uint32_t b_kb = (uint32_t)(((lane >> 3) & 1) * 8) * 2;

    for (int kt = 0; kt < KTILES; kt++) {
        CP_WAIT3();
        __syncthreads();   // single barrier per ktile (stage being overwritten was
                           // last read in iteration kt-1; this barrier separates them)
        const uint32_t st = sbase + (uint32_t)(kt % NSTAGE) * STB;
        const uint32_t sX = st, sA = st + XTB;
#pragma unroll
        for (int kk = 0; kk < 2; kk++) {
            const uint32_t acol = a_colb + kk * 32;
            const uint32_t bcol = b_kb + kk * 32;
            uint32_t ax[2][4];
            ldsm_x4(ax[0], sX + a_row * (PADK * 2) + acol);
            ldsm_x4(ax[1], sX + (a_row + 16) * (PADK * 2) + acol);
            uint32_t bb[8][2];
#pragma unroll
            for (int j = 0; j < 4; j++) {
                uint32_t r[4];
                ldsm_x4(r, sA + (b_nrow + j * 16) * (PADK * 2) + bcol);
                bb[2 * j][0] = r[0]; bb[2 * j][1] = r[1];
                bb[2 * j + 1][0] = r[2]; bb[2 * j + 1][1] = r[3];
            }
#pragma unroll
            for (int mi = 0; mi < 2; mi++)
#pragma unroll
                for (int nj = 0; nj < 8; nj++)
                    mma_f16(acc[mi][nj], ax[mi], bb[nj]);
        }
        if (kt + 4 < KTILES)
            load_stage_async(sbase + (uint32_t)((kt + 4) % NSTAGE) * STB,
                             Xh, Ath, bm, bn, kt + 4, tid);
        CP_COMMIT();   // unconditional: keeps wait_group(3) retiring correctly
    }

    // epilogue
    const int er = lane >> 2, ec = (lane & 3) * 2;
#pragma unroll
    for (int mi = 0; mi < 2; mi++) {
        const int row = bm * 128 + warp_m * 32 + mi * 16 + er;
#pragma unroll
        for (int nt = 0; nt < 8; nt++) {
            const int col = bn * 128 + warp_n * 64 + nt * 8 + ec;
            *reinterpret_cast<float2*>(out + (size_t)row * DD + col) =
                make_float2(acc[mi][nt][0], acc[mi][nt][1]);
            *reinterpret_cast<float2*>(out + (size_t)(row + 8) * DD + col) =
                make_float2(acc[mi][nt][2], acc[mi][nt][3]);
        }
    }
}

// ---------------------------------------------------------------------------
extern "C" void kernel_launch(void* const* d_in, const int* in_sizes, int n_in,
                              void* d_out, int out_size) {
    const float* x  = (const float*)d_in[0];
    const float* W  = (const float*)d_in[1];
    const float* k1 = (const float*)d_in[2];
    const float* k2 = (const float*)d_in[3];
    const float* k3 = (const float*)d_in[4];
    float* out = (float*)d_out;

    float *buf0, *buf1, *k12;
    __half *xh, *ath;
    cudaGetSymbolAddress((void**)&buf0, g_buf0);
    cudaGetSymbolAddress((void**)&buf1, g_buf1);
    cudaGetSymbolAddress((void**)&k12, g_k12);
    cudaGetSymbolAddress((void**)&xh, g_Xh);
    cudaGetSymbolAddress((void**)&ath, g_Ath);

    {
        size_t n8 = (size_t)MROWS * DD / 8;
        cvt_x_kernel<<<(unsigned)(n8 / 256), 256>>>(x, xh);
    }
    kron12_kernel<<<1, 1024>>>(k1, k2, k12);
    {
        dim3 grid(DD / 32, DD / 32), block(32, 8);
        transpose_kernel<<<grid, block>>>(W, buf0);
    }
    {
        dim3 grid(DD / 256, DD), block(256);
        stage3_kernel<<<grid, block>>>(buf0, buf1, k3);    // buf1 = T1
        stage12_kernel<<<grid, block>>>(buf1, buf0, k12);  // buf0 = A
    }
    {
        dim3 grid(DD / 32, DD / 32), block(32, 8);
        cvt_at_kernel<<<grid, block>>>(buf0, ath);
    }
    {
        static bool attr_set = false;
        if (!attr_set) {
            cudaFuncSetAttribute(gemm_hmma_kernel,
                                 cudaFuncAttributeMaxDynamicSharedMemorySize, GEMM_SMEM);
            attr_set = true;
        }
        dim3 grid(DD / 128, MROWS / 128);   // (10, 128)
        gemm_hmma_kernel<<<grid, 256, GEMM_SMEM>>>(xh, ath, out);
    }
}

// round 12
// speedup vs baseline: 1.1074x; 1.0598x over previous
#include <cuda_runtime.h>
#include <cuda_fp16.h>
#include <cstdint>

// out[16384,1280] = x[16384,1280] @ A[1280,1280],  A = (k1 (x) k2 (x) k3) @ W^T
// Kron factorization in fp32, then SINGLE-product fp16 HMMA GEMM:
//   D = fp16(x) * fp16(A^T)   (fp32 accumulate)  rel_err ~2.9e-4 (validated)
// R11: stage kernels register-tiled — 8 outputs per input-column load
// (cuts the 40x/32x L2 re-read to 5x/4x) while keeping the R1 thread shape
// that R9/R10 proved necessary (big grid, no smem occupancy cliff).

#define DD 1280
#define MROWS 16384

__device__ float g_buf0[DD * DD];
__device__ float g_buf1[DD * DD];
__device__ float g_k12[32 * 32];
__device__ __half g_Xh[(size_t)MROWS * DD];
__device__ __half g_Ath[DD * DD];   // fp16(A^T): [n][k], k contiguous

// ---------------------------------------------------------------------------
__device__ __forceinline__ uint32_t smem_u32(const void* p) {
    uint32_t a;
    asm("{ .reg .u64 t; cvta.to.shared.u64 t, %1; cvt.u32.u64 %0, t; }" : "=r"(a) : "l"(p));
    return a;
}
__device__ __forceinline__ void ldsm_x4(uint32_t* r, uint32_t addr) {
    asm volatile("ldmatrix.sync.aligned.m8n8.x4.shared.b16 {%0,%1,%2,%3}, [%4];"
                 : "=r"(r[0]), "=r"(r[1]), "=r"(r[2]), "=r"(r[3]) : "r"(addr));
}
__device__ __forceinline__ void mma_f16(float* c, const uint32_t* a, const uint32_t* b) {
    asm volatile("mma.sync.aligned.m16n8k16.row.col.f32.f16.f16.f32 "
                 "{%0,%1,%2,%3}, {%4,%5,%6,%7}, {%8,%9}, {%0,%1,%2,%3};"
                 : "+f"(c[0]), "+f"(c[1]), "+f"(c[2]), "+f"(c[3])
                 : "r"(a[0]), "r"(a[1]), "r"(a[2]), "r"(a[3]), "r"(b[0]), "r"(b[1]));
}
#define CP16(dst, src) \
    asm volatile("cp.async.cg.shared.global [%0], [%1], 16;" :: "r"(dst), "l"(src))
#define CP_COMMIT() asm volatile("cp.async.commit_group;" ::: "memory")
#define CP_WAIT3()  asm volatile("cp.async.wait_group 3;" ::: "memory")

// ---------------------------------------------------------------------------
// Prologue chain (fp32)
// ---------------------------------------------------------------------------
__global__ void transpose_kernel(const float* __restrict__ W, float* __restrict__ Wt) {
    __shared__ float tile[32][33];
    const int j0 = blockIdx.x * 32, o0 = blockIdx.y * 32;
    const int tx = threadIdx.x, ty = threadIdx.y;
#pragma unroll
    for (int r = 0; r < 32; r += 8)
        tile[ty + r][tx] = W[(o0 + ty + r) * DD + (j0 + tx)];
    __syncthreads();
#pragma unroll
    for (int r = 0; r < 32; r += 8)
        Wt[(j0 + ty + r) * DD + (o0 + tx)] = tile[tx][ty + r];
}
// k12 = kron(k1, k2)
__global__ void kron12_kernel(const float* __restrict__ k1, const float* __restrict__ k2,
                              float* __restrict__ k12) {
    const int t = threadIdx.x;              // 0..1023
    const int r = t >> 5, c = t & 31;
    k12[t] = k1[(r >> 3) * 4 + (c >> 3)] * k2[(r & 7) * 8 + (c & 7)];
}
// Stage 3, register-tiled: block = (o-tile 256, g*5 + a3grp); thread loads its
// column of 40 source rows once, emits 8 a3 outputs.
__global__ __launch_bounds__(256)
void stage3_kernel(const float* __restrict__ src, float* __restrict__ dst,
                   const float* __restrict__ k3) {
    const int tid = threadIdx.x;
    const int o = blockIdx.x * 256 + tid;
    const int g = blockIdx.y / 5;
    const int a3b = (blockIdx.y % 5) * 8;   // first of 8 a3 outputs

    __shared__ float sk[8][40];
    for (int i = tid; i < 320; i += 256)
        sk[i / 40][i % 40] = k3[(a3b + i / 40) * 40 + (i % 40)];
    __syncthreads();

    const float* s = src + (g * 40) * DD + o;
    float v[40];
#pragma unroll
    for (int b3 = 0; b3 < 40; b3++) v[b3] = s[b3 * DD];

#pragma unroll
    for (int j = 0; j < 8; j++) {
        float acc0 = 0.f, acc1 = 0.f;
#pragma unroll
        for (int b3 = 0; b3 < 40; b3 += 2) {
            acc0 += sk[j][b3] * v[b3];
            acc1 += sk[j][b3 + 1] * v[b3 + 1];
        }
        dst[(g * 40 + a3b + j) * DD + o] = acc0 + acc1;
    }
}
// Fused stage2+stage1, register-tiled: block = (o-tile 256, a3*4 + cgrp);
// thread loads its column of 32 source rows once, emits 8 c12 outputs.
__global__ __launch_bounds__(256)
void stage12_kernel(const float* __restrict__ src, float* __restrict__ dst,
                    const float* __restrict__ k12) {
    const int tid = threadIdx.x;
    const int o = blockIdx.x * 256 + tid;
    const int a3 = blockIdx.y >> 2;
    const int cb = (blockIdx.y & 3) * 8;    // first of 8 c12 outputs

    __shared__ float sk[8][32];
    if (tid < 256)
        sk[tid >> 5][tid & 31] = k12[(cb + (tid >> 5)) * 32 + (tid & 31)];
    __syncthreads();

    const float* s = src + a3 * DD + o;
    float v[32];
#pragma unroll
    for (int b12 = 0; b12 < 32; b12++) v[b12] = s[b12 * 40 * DD];

#pragma unroll
    for (int j = 0; j < 8; j++) {
        float acc0 = 0.f, acc1 = 0.f;
#pragma unroll
        for (int b12 = 0; b12 < 32; b12 += 2) {
            acc0 += sk[j][b12] * v[b12];
            acc1 += sk[j][b12 + 1] * v[b12 + 1];
        }
        dst[((cb + j) * 40 + a3) * DD + o] = acc0 + acc1;
    }
}
// x -> fp16, 8 elems/thread
__global__ void cvt_x_kernel(const float* __restrict__ x, __half* __restrict__ xh) {
    const size_t i8 = ((size_t)blockIdx.x * 256 + threadIdx.x) * 8;
    float4 v0 = *reinterpret_cast<const float4*>(x + i8);
    float4 v1 = *reinterpret_cast<const float4*>(x + i8 + 4);
    __half2 a = __floats2half2_rn(v0.x, v0.y);
    __half2 b = __floats2half2_rn(v0.z, v0.w);
    __half2 c = __floats2half2_rn(v1.x, v1.y);
    __half2 d = __floats2half2_rn(v1.z, v1.w);
    uint4 o;
    o.x = *reinterpret_cast<uint32_t*>(&a);
    o.y = *reinterpret_cast<uint32_t*>(&b);
    o.z = *reinterpret_cast<uint32_t*>(&c);
    o.w = *reinterpret_cast<uint32_t*>(&d);
    *reinterpret_cast<uint4*>(xh + i8) = o;
}
// A[k][n] -> fp16(At[n][k])
__global__ void cvt_at_kernel(const float* __restrict__ A, __half* __restrict__ ath) {
    __shared__ float t[32][33];
    const int k0 = blockIdx.x * 32, n0 = blockIdx.y * 32;
    const int tx = threadIdx.x, ty = threadIdx.y;
#pragma unroll
    for (int r = 0; r < 32; r += 8)
        t[ty + r][tx] = A[(k0 + ty + r) * DD + (n0 + tx)];
    __syncthreads();
#pragma unroll
    for (int r = 0; r < 32; r += 8)
        ath[(n0 + ty + r) * DD + (k0 + tx)] = __float2half_rn(t[tx][ty + r]);
}

// ---------------------------------------------------------------------------
// Single-product fp16 HMMA GEMM. CTA tile 128x128, BK=32, 256 threads,
// NSTAGE=5, 2 CTAs/SM, ONE barrier per ktile. (validated R8 config)
// ---------------------------------------------------------------------------
#define BK 32
#define PADK 40
#define XTB (128 * PADK * 2)        // 10240 B per tile
#define STB (2 * XTB)               // stage: Xh, Ath = 20480 B
#define NSTAGE 5
#define GEMM_SMEM (NSTAGE * STB)    // 102400 B
#define KTILES (DD / BK)            // 40

__device__ __forceinline__ void load_stage_async(
    uint32_t sdst,
    const __half* __restrict__ Xh, const __half* __restrict__ Ath,
    int bm, int bn, int kt, int tid) {
    const int kofs = kt * BK;
#pragma unroll
    for (int i = 0; i < 2; i++) {
        int idx = i * 256 + tid;          // 0..511
        int row = idx >> 2, c = idx & 3;
        uint32_t so = (uint32_t)(row * (PADK * 2) + c * 16);
        size_t gx = (size_t)(bm * 128 + row) * DD + kofs + c * 8;
        size_t ga = (size_t)(bn * 128 + row) * DD + kofs + c * 8;
        CP16(sdst + so,       Xh  + gx);
        CP16(sdst + XTB + so, Ath + ga);
    }
}

__global__ __launch_bounds__(256, 2)
void gemm_hmma_kernel(const __half* __restrict__ Xh,
                      const __half* __restrict__ Ath,
                      float* __restrict__ out) {
    extern __shared__ __align__(128) char smem[];
    const uint32_t sbase = smem_u32(smem);
    const int tid = threadIdx.x, lane = tid & 31, wid = tid >> 5;
    const int warp_m = wid & 3, warp_n = wid >> 2;   // 4 x 2 warps, tile 32x64
    const int bn = blockIdx.x, bm = blockIdx.y;

    float acc[2][8][4];
#pragma unroll
    for (int a = 0; a < 2; a++)
#pragma unroll
        for (int b = 0; b < 8; b++)
#pragma unroll
            for (int c = 0; c < 4; c++) acc[a][b][c] = 0.f;

#pragma unroll
    for (int p = 0; p < 4; p++) {
        load_stage_async(sbase + (uint32_t)p * STB, Xh, Ath, bm, bn, p, tid);
        CP_COMMIT();
    }

    const uint32_t a_row = (uint32_t)(warp_m * 32 + (lane & 7) + ((lane >> 3) & 1) * 8);
    const uint32_t a_colb = (uint32_t)(((lane >> 4) & 1) * 8) * 2;
    const uint32_t b_nrow = (uint32_t)(warp_n * 64 + (lane & 7) + ((lane >> 4) & 1) * 8);
    const uint32_t b_kb = (uint32_t)(((lane >> 3) & 1) * 8) * 2;

    for (int kt = 0; kt < KTILES; kt++) {
        CP_WAIT3();
        __syncthreads();   // single barrier per ktile
        const uint32_t st = sbase + (uint32_t)(kt % NSTAGE) * STB;
        const uint32_t sX = st, sA = st + XTB;
#pragma unroll
        for (int kk = 0; kk < 2; kk++) {
            const uint32_t acol = a_colb + kk * 32;
            const uint32_t bcol = b_kb + kk * 32;
            uint32_t ax[2][4];
            ldsm_x4(ax[0], sX + a_row * (PADK * 2) + acol);
            ldsm_x4(ax[1], sX + (a_row + 16) * (PADK * 2) + acol);
            uint32_t bb[8][2];
#pragma unroll
            for (int j = 0; j < 4; j++) {
                uint32_t r[4];
                ldsm_x4(r, sA + (b_nrow + j * 16) * (PADK * 2) + bcol);
                bb[2 * j][0] = r[0]; bb[2 * j][1] = r[1];
                bb[2 * j + 1][0] = r[2]; bb[2 * j + 1][1] = r[3];
            }
#pragma unroll
            for (int mi = 0; mi < 2; mi++)
#pragma unroll
                for (int nj = 0; nj < 8; nj++)
                    mma_f16(acc[mi][nj], ax[mi], bb[nj]);
        }
        if (kt + 4 < KTILES)
            load_stage_async(sbase + (uint32_t)((kt + 4) % NSTAGE) * STB,
                             Xh, Ath, bm, bn, kt + 4, tid);
        CP_COMMIT();
    }

    // epilogue
    const int er = lane >> 2, ec = (lane & 3) * 2;
#pragma unroll
    for (int mi = 0; mi < 2; mi++) {
        const int row = bm * 128 + warp_m * 32 + mi * 16 + er;
#pragma unroll
        for (int nt = 0; nt < 8; nt++) {
            const int col = bn * 128 + warp_n * 64 + nt * 8 + ec;
            *reinterpret_cast<float2*>(out + (size_t)row * DD + col) =
                make_float2(acc[mi][nt][0], acc[mi][nt][1]);
            *reinterpret_cast<float2*>(out + (size_t)(row + 8) * DD + col) =
                make_float2(acc[mi][nt][2], acc[mi][nt][3]);
        }
    }
}

// ---------------------------------------------------------------------------
extern "C" void kernel_launch(void* const* d_in, const int* in_sizes, int n_in,
                              void* d_out, int out_size) {
    const float* x  = (const float*)d_in[0];
    const float* W  = (const float*)d_in[1];
    const float* k1 = (const float*)d_in[2];
    const float* k2 = (const float*)d_in[3];
    const float* k3 = (const float*)d_in[4];
    float* out = (float*)d_out;

    float *buf0, *buf1, *k12;
    __half *xh, *ath;
    cudaGetSymbolAddress((void**)&buf0, g_buf0);
    cudaGetSymbolAddress((void**)&buf1, g_buf1);
    cudaGetSymbolAddress((void**)&k12, g_k12);
    cudaGetSymbolAddress((void**)&xh, g_Xh);
    cudaGetSymbolAddress((void**)&ath, g_Ath);

    {
        size_t n8 = (size_t)MROWS * DD / 8;
        cvt_x_kernel<<<(unsigned)(n8 / 256), 256>>>(x, xh);
    }
    kron12_kernel<<<1, 1024>>>(k1, k2, k12);
    {
        dim3 grid(DD / 32, DD / 32), block(32, 8);
        transpose_kernel<<<grid, block>>>(W, buf0);
    }
    {
        dim3 g3(DD / 256, 32 * 5);              // (o-tile, g*5 + a3grp)
        stage3_kernel<<<g3, 256>>>(buf0, buf1, k3);     // buf1 = T1
        dim3 g12(DD / 256, 40 * 4);             // (o-tile, a3*4 + cgrp)
        stage12_kernel<<<g12, 256>>>(buf1, buf0, k12);  // buf0 = A
    }
    {
        dim3 grid(DD / 32, DD / 32), block(32, 8);
        cvt_at_kernel<<<grid, block>>>(buf0, ath);
    }
    {
        static bool attr_set = false;
        if (!attr_set) {
            cudaFuncSetAttribute(gemm_hmma_kernel,
                                 cudaFuncAttributeMaxDynamicSharedMemorySize, GEMM_SMEM);
            attr_set = true;
        }
        dim3 grid(DD / 128, MROWS / 128);   // (10, 128)
        gemm_hmma_kernel<<<grid, 256, GEMM_SMEM>>>(xh, ath, out);
    }
}

// round 13
// speedup vs baseline: 1.1176x; 1.0092x over previous
#include <cuda_runtime.h>
#include <cuda_fp16.h>
#include <cstdint>

// out[16384,1280] = x[16384,1280] @ A[1280,1280],  A = (k1 (x) k2 (x) k3) @ W^T
// Kron factorization in fp32, then SINGLE-product fp16 HMMA GEMM:
//   D = fp16(x) * fp16(A^T)   (fp32 accumulate)  rel_err ~2.9e-4 (validated)
// R12: cvt_x forked onto a second stream, overlapping with the independent
// A-chain (transpose -> stage3 -> stage12 -> cvt_at); join before GEMM.
// GEMM + stage kernels unchanged from R11 (validated).

#define DD 1280
#define MROWS 16384

__device__ float g_buf0[DD * DD];
__device__ float g_buf1[DD * DD];
__device__ float g_k12[32 * 32];
__device__ __half g_Xh[(size_t)MROWS * DD];
__device__ __half g_Ath[DD * DD];   // fp16(A^T): [n][k], k contiguous

// ---------------------------------------------------------------------------
__device__ __forceinline__ uint32_t smem_u32(const void* p) {
    uint32_t a;
    asm("{ .reg .u64 t; cvta.to.shared.u64 t, %1; cvt.u32.u64 %0, t; }" : "=r"(a) : "l"(p));
    return a;
}
__device__ __forceinline__ void ldsm_x4(uint32_t* r, uint32_t addr) {
    asm volatile("ldmatrix.sync.aligned.m8n8.x4.shared.b16 {%0,%1,%2,%3}, [%4];"
                 : "=r"(r[0]), "=r"(r[1]), "=r"(r[2]), "=r"(r[3]) : "r"(addr));
}
__device__ __forceinline__ void mma_f16(float* c, const uint32_t* a, const uint32_t* b) {
    asm volatile("mma.sync.aligned.m16n8k16.row.col.f32.f16.f16.f32 "
                 "{%0,%1,%2,%3}, {%4,%5,%6,%7}, {%8,%9}, {%0,%1,%2,%3};"
                 : "+f"(c[0]), "+f"(c[1]), "+f"(c[2]), "+f"(c[3])
                 : "r"(a[0]), "r"(a[1]), "r"(a[2]), "r"(a[3]), "r"(b[0]), "r"(b[1]));
}
#define CP16(dst, src) \
    asm volatile("cp.async.cg.shared.global [%0], [%1], 16;" :: "r"(dst), "l"(src))
#define CP_COMMIT() asm volatile("cp.async.commit_group;" ::: "memory")
#define CP_WAIT3()  asm volatile("cp.async.wait_group 3;" ::: "memory")

// ---------------------------------------------------------------------------
// Prologue chain (fp32)
// ---------------------------------------------------------------------------
__global__ void transpose_kernel(const float* __restrict__ W, float* __restrict__ Wt) {
    __shared__ float tile[32][33];
    const int j0 = blockIdx.x * 32, o0 = blockIdx.y * 32;
    const int tx = threadIdx.x, ty = threadIdx.y;
#pragma unroll
    for (int r = 0; r < 32; r += 8)
        tile[ty + r][tx] = W[(o0 + ty + r) * DD + (j0 + tx)];
    __syncthreads();
#pragma unroll
    for (int r = 0; r < 32; r += 8)
        Wt[(j0 + ty + r) * DD + (o0 + tx)] = tile[tx][ty + r];
}
// k12 = kron(k1, k2)
__global__ void kron12_kernel(const float* __restrict__ k1, const float* __restrict__ k2,
                              float* __restrict__ k12) {
    const int t = threadIdx.x;              // 0..1023
    const int r = t >> 5, c = t & 31;
    k12[t] = k1[(r >> 3) * 4 + (c >> 3)] * k2[(r & 7) * 8 + (c & 7)];
}
// Stage 3, register-tiled: 8 outputs per input-column load (R11, validated)
__global__ __launch_bounds__(256)
void stage3_kernel(const float* __restrict__ src, float* __restrict__ dst,
                   const float* __restrict__ k3) {
    const int tid = threadIdx.x;
    const int o = blockIdx.x * 256 + tid;
    const int g = blockIdx.y / 5;
    const int a3b = (blockIdx.y % 5) * 8;

    __shared__ float sk[8][40];
    for (int i = tid; i < 320; i += 256)
        sk[i / 40][i % 40] = k3[(a3b + i / 40) * 40 + (i % 40)];
    __syncthreads();

    const float* s = src + (g * 40) * DD + o;
    float v[40];
#pragma unroll
    for (int b3 = 0; b3 < 40; b3++) v[b3] = s[b3 * DD];

#pragma unroll
    for (int j = 0; j < 8; j++) {
        float acc0 = 0.f, acc1 = 0.f;
#pragma unroll
        for (int b3 = 0; b3 < 40; b3 += 2) {
            acc0 += sk[j][b3] * v[b3];
            acc1 += sk[j][b3 + 1] * v[b3 + 1];
        }
        dst[(g * 40 + a3b + j) * DD + o] = acc0 + acc1;
    }
}
// Fused stage2+stage1, register-tiled (R11, validated)
__global__ __launch_bounds__(256)
void stage12_kernel(const float* __restrict__ src, float* __restrict__ dst,
                    const float* __restrict__ k12) {
    const int tid = threadIdx.x;
    const int o = blockIdx.x * 256 + tid;
    const int a3 = blockIdx.y >> 2;
    const int cb = (blockIdx.y & 3) * 8;

    __shared__ float sk[8][32];
    if (tid < 256)
        sk[tid >> 5][tid & 31] = k12[(cb + (tid >> 5)) * 32 + (tid & 31)];
    __syncthreads();

    const float* s = src + a3 * DD + o;
    float v[32];
#pragma unroll
    for (int b12 = 0; b12 < 32; b12++) v[b12] = s[b12 * 40 * DD];

#pragma unroll
    for (int j = 0; j < 8; j++) {
        float acc0 = 0.f, acc1 = 0.f;
#pragma unroll
        for (int b12 = 0; b12 < 32; b12 += 2) {
            acc0 += sk[j][b12] * v[b12];
            acc1 += sk[j][b12 + 1] * v[b12 + 1];
        }
        dst[((cb + j) * 40 + a3) * DD + o] = acc0 + acc1;
    }
}
// x -> fp16, 8 elems/thread
__global__ void cvt_x_kernel(const float* __restrict__ x, __half* __restrict__ xh) {
    const size_t i8 = ((size_t)blockIdx.x * 256 + threadIdx.x) * 8;
    float4 v0 = *reinterpret_cast<const float4*>(x + i8);
    float4 v1 = *reinterpret_cast<const float4*>(x + i8 + 4);
    __half2 a = __floats2half2_rn(v0.x, v0.y);
    __half2 b = __floats2half2_rn(v0.z, v0.w);
    __half2 c = __floats2half2_rn(v1.x, v1.y);
    __half2 d = __floats2half2_rn(v1.z, v1.w);
    uint4 o;
    o.x = *reinterpret_cast<uint32_t*>(&a);
    o.y = *reinterpret_cast<uint32_t*>(&b);
    o.z = *reinterpret_cast<uint32_t*>(&c);
    o.w = *reinterpret_cast<uint32_t*>(&d);
    *reinterpret_cast<uint4*>(xh + i8) = o;
}
// A[k][n] -> fp16(At[n][k])
__global__ void cvt_at_kernel(const float* __restrict__ A, __half* __restrict__ ath) {
    __shared__ float t[32][33];
    const int k0 = blockIdx.x * 32, n0 = blockIdx.y * 32;
    const int tx = threadIdx.x, ty = threadIdx.y;
#pragma unroll
    for (int r = 0; r < 32; r += 8)
        t[ty + r][tx] = A[(k0 + ty + r) * DD + (n0 + tx)];
    __syncthreads();
#pragma unroll
    for (int r = 0; r < 32; r += 8)
        ath[(n0 + ty + r) * DD + (k0 + tx)] = __float2half_rn(t[tx][ty + r]);
}

// ---------------------------------------------------------------------------
// Single-product fp16 HMMA GEMM. CTA tile 128x128, BK=32, 256 threads,
// NSTAGE=5, 2 CTAs/SM, ONE barrier per ktile. (validated config)
// ---------------------------------------------------------------------------
#define BK 32
#define PADK 40
#define XTB (128 * PADK * 2)        // 10240 B per tile
#define STB (2 * XTB)               // stage: Xh, Ath = 20480 B
#define NSTAGE 5
#define GEMM_SMEM (NSTAGE * STB)    // 102400 B
#define KTILES (DD / BK)            // 40

__device__ __forceinline__ void load_stage_async(
    uint32_t sdst,
    const __half* __restrict__ Xh, const __half* __restrict__ Ath,
    int bm, int bn, int kt, int tid) {
    const int kofs = kt * BK;
#pragma unroll
    for (int i = 0; i < 2; i++) {
        int idx = i * 256 + tid;          // 0..511
        int row = idx >> 2, c = idx & 3;
        uint32_t so = (uint32_t)(row * (PADK * 2) + c * 16);
        size_t gx = (size_t)(bm * 128 + row) * DD + kofs + c * 8;
        size_t ga = (size_t)(bn * 128 + row) * DD + kofs + c * 8;
        CP16(sdst + so,       Xh  + gx);
        CP16(sdst + XTB + so, Ath + ga);
    }
}

__global__ __launch_bounds__(256, 2)
void gemm_hmma_kernel(const __half* __restrict__ Xh,
                      const __half* __restrict__ Ath,
                      float* __restrict__ out) {
    extern __shared__ __align__(128) char smem[];
    const uint32_t sbase = smem_u32(smem);
    const int tid = threadIdx.x, lane = tid & 31, wid = tid >> 5;
    const int warp_m = wid & 3, warp_n = wid >> 2;   // 4 x 2 warps, tile 32x64
    const int bn = blockIdx.x, bm = blockIdx.y;

    float acc[2][8][4];
#pragma unroll
    for (int a = 0; a < 2; a++)
#pragma unroll
        for (int b = 0; b < 8; b++)
#pragma unroll
            for (int c = 0; c < 4; c++) acc[a][b][c] = 0.f;

#pragma unroll
    for (int p = 0; p < 4; p++) {
        load_stage_async(sbase + (uint32_t)p * STB, Xh, Ath, bm, bn, p, tid);
        CP_COMMIT();
    }

    const uint32_t a_row = (uint32_t)(warp_m * 32 + (lane & 7) + ((lane >> 3) & 1) * 8);
    const uint32_t a_colb = (uint32_t)(((lane >> 4) & 1) * 8) * 2;
    const uint32_t b_nrow = (uint32_t)(warp_n * 64 + (lane & 7) + ((lane >> 4) & 1) * 8);
    const uint32_t b_kb = (uint32_t)(((lane >> 3) & 1) * 8) * 2;

    for (int kt = 0; kt < KTILES; kt++) {
        CP_WAIT3();
        __syncthreads();   // single barrier per ktile
        const uint32_t st = sbase + (uint32_t)(kt % NSTAGE) * STB;
        const uint32_t sX = st, sA = st + XTB;
#pragma unroll
        for (int kk = 0; kk < 2; kk++) {
            const uint32_t acol = a_colb + kk * 32;
            const uint32_t bcol = b_kb + kk * 32;
            uint32_t ax[2][4];
            ldsm_x4(ax[0], sX + a_row * (PADK * 2) + acol);
            ldsm_x4(ax[1], sX + (a_row + 16) * (PADK * 2) + acol);
            uint32_t bb[8][2];
#pragma unroll
            for (int j = 0; j < 4; j++) {
                uint32_t r[4];
                ldsm_x4(r, sA + (b_nrow + j * 16) * (PADK * 2) + bcol);
                bb[2 * j][0] = r[0]; bb[2 * j][1] = r[1];
                bb[2 * j + 1][0] = r[2]; bb[2 * j + 1][1] = r[3];
            }
#pragma unroll
            for (int mi = 0; mi < 2; mi++)
#pragma unroll
                for (int nj = 0; nj < 8; nj++)
                    mma_f16(acc[mi][nj], ax[mi], bb[nj]);
        }
        if (kt + 4 < KTILES)
            load_stage_async(sbase + (uint32_t)((kt + 4) % NSTAGE) * STB,
                             Xh, Ath, bm, bn, kt + 4, tid);
        CP_COMMIT();
    }

    // epilogue
    const int er = lane >> 2, ec = (lane & 3) * 2;
#pragma unroll
    for (int mi = 0; mi < 2; mi++) {
        const int row = bm * 128 + warp_m * 32 + mi * 16 + er;
#pragma unroll
        for (int nt = 0; nt < 8; nt++) {
            const int col = bn * 128 + warp_n * 64 + nt * 8 + ec;
            *reinterpret_cast<float2*>(out + (size_t)row * DD + col) =
                make_float2(acc[mi][nt][0], acc[mi][nt][1]);
            *reinterpret_cast<float2*>(out + (size_t)(row + 8) * DD + col) =
                make_float2(acc[mi][nt][2], acc[mi][nt][3]);
        }
    }
}

// ---------------------------------------------------------------------------
extern "C" void kernel_launch(void* const* d_in, const int* in_sizes, int n_in,
                              void* d_out, int out_size) {
    const float* x  = (const float*)d_in[0];
    const float* W  = (const float*)d_in[1];
    const float* k1 = (const float*)d_in[2];
    const float* k2 = (const float*)d_in[3];
    const float* k3 = (const float*)d_in[4];
    float* out = (float*)d_out;

    float *buf0, *buf1, *k12;
    __half *xh, *ath;
    cudaGetSymbolAddress((void**)&buf0, g_buf0);
    cudaGetSymbolAddress((void**)&buf1, g_buf1);
    cudaGetSymbolAddress((void**)&k12, g_k12);
    cudaGetSymbolAddress((void**)&xh, g_Xh);
    cudaGetSymbolAddress((void**)&ath, g_Ath);

    // One-time host-object setup (no device memory involved).
    static cudaStream_t s2 = nullptr;
    static cudaEvent_t ev_fork = nullptr, ev_join = nullptr;
    static bool attr_set = false;
    if (!attr_set) {
        cudaFuncSetAttribute(gemm_hmma_kernel,
                             cudaFuncAttributeMaxDynamicSharedMemorySize, GEMM_SMEM);
        cudaStreamCreateWithFlags(&s2, cudaStreamNonBlocking);
        cudaEventCreateWithFlags(&ev_fork, cudaEventDisableTiming);
        cudaEventCreateWithFlags(&ev_join, cudaEventDisableTiming);
        attr_set = true;
    }

    // Fork: cvt_x (independent of the A-chain) runs on s2 concurrently.
    cudaEventRecord(ev_fork, 0);
    cudaStreamWaitEvent(s2, ev_fork, 0);
    {
        size_t n8 = (size_t)MROWS * DD / 8;
        cvt_x_kernel<<<(unsigned)(n8 / 256), 256, 0, s2>>>(x, xh);
    }
    cudaEventRecord(ev_join, s2);

    // A-chain on the main (capture) stream.
    kron12_kernel<<<1, 1024>>>(k1, k2, k12);
    {
        dim3 grid(DD / 32, DD / 32), block(32, 8);
        transpose_kernel<<<grid, block>>>(W, buf0);
    }
    {
        dim3 g3(DD / 256, 32 * 5);
        stage3_kernel<<<g3, 256>>>(buf0, buf1, k3);     // buf1 = T1
        dim3 g12(DD / 256, 40 * 4);
        stage12_kernel<<<g12, 256>>>(buf1, buf0, k12);  // buf0 = A
    }
    {
        dim3 grid(DD / 32, DD / 32), block(32, 8);
        cvt_at_kernel<<<grid, block>>>(buf0, ath);
    }

    // Join: GEMM needs both Xh (s2) and Ath (main stream).
    cudaStreamWaitEvent(0, ev_join, 0);
    {
        dim3 grid(DD / 128, MROWS / 128);   // (10, 128)
        gemm_hmma_kernel<<<grid, 256, GEMM_SMEM>>>(xh, ath, out);
    }
}